// round 13
// baseline (speedup 1.0000x reference)
#include <cuda_runtime.h>
#include <cuda_fp16.h>
#include <cstdint>

#define SEQ 2048
#define NB  32
#define DIM 128
#define NTOK (NB*SEQ)
#define TOK 128
#define NTILES (NTOK/TOK)      // 512
#define GRID 128               // all co-resident (1 CTA/SM), 4 tiles each
#define NTHR 512               // 16 warps

// ---------------- scratch (no allocations allowed) ----------------
__device__ __align__(16) __half g_h0[NTOK*DIM];
__device__ __align__(16) __half g_h1[NTOK*DIM];
__device__ float g_part[NB*DIM];
__device__ __align__(16) __half g_Whi[4][DIM*DIM];
__device__ __align__(16) __half g_Wlo[4][DIM*DIM];
__device__ unsigned g_ctr;     // monotonic grid-barrier counter (replay-safe)

// ---------------- helpers ----------------
__device__ __forceinline__ uint32_t smem_u32(const void* p) {
    uint32_t a;
    asm("{ .reg .u64 t; cvta.to.shared.u64 t, %1; cvt.u32.u64 %0, t; }" : "=r"(a) : "l"(p));
    return a;
}
__device__ __forceinline__ void sts128(uint32_t addr, uint4 v) {
    asm volatile("st.shared.v4.b32 [%0], {%1,%2,%3,%4};" :: "r"(addr), "r"(v.x), "r"(v.y), "r"(v.z), "r"(v.w) : "memory");
}
__device__ __forceinline__ uint4 lds128(uint32_t addr) {
    uint4 v;
    asm volatile("ld.shared.v4.b32 {%0,%1,%2,%3}, [%4];"
        : "=r"(v.x), "=r"(v.y), "=r"(v.z), "=r"(v.w) : "r"(addr));
    return v;
}
__device__ __forceinline__ void cpasync16(uint32_t dst, const void* src) {
    asm volatile("cp.async.cg.shared.global [%0], [%1], 16;" :: "r"(dst), "l"(src) : "memory");
}
#define CP_COMMIT() asm volatile("cp.async.commit_group;" ::: "memory")
#define CP_WAIT0()  asm volatile("cp.async.wait_group 0;" ::: "memory")
#define LDMX4(r, addr) \
    asm volatile("ldmatrix.sync.aligned.m8n8.x4.shared.b16 {%0,%1,%2,%3}, [%4];" \
        : "=r"((r)[0]), "=r"((r)[1]), "=r"((r)[2]), "=r"((r)[3]) : "r"(addr))
__device__ __forceinline__ void mma16816(float* d, const uint32_t* a, const uint32_t* b) {
    asm volatile(
        "mma.sync.aligned.m16n8k16.row.col.f32.f16.f16.f32 "
        "{%0,%1,%2,%3}, {%4,%5,%6,%7}, {%8,%9}, {%0,%1,%2,%3};"
        : "+f"(d[0]), "+f"(d[1]), "+f"(d[2]), "+f"(d[3])
        : "r"(a[0]), "r"(a[1]), "r"(a[2]), "r"(a[3]), "r"(b[0]), "r"(b[1]));
}
__device__ __forceinline__ uint32_t tswz(int row, int kchunk) {
    return (uint32_t)(row * 256 + ((kchunk ^ (row & 7)) << 4));
}
__device__ __forceinline__ uint32_t packh(float a, float b) {
    __half2 t = __floats2half2_rn(a, b);
    return *reinterpret_cast<uint32_t*>(&t);
}

// replay-safe grid barrier: monotonic counter, release->acquire via threadfence
__device__ __forceinline__ void grid_barrier() {
    __syncthreads();
    if (threadIdx.x == 0) {
        __threadfence();
        const unsigned t = atomicAdd(&g_ctr, 1u) + 1u;
        const unsigned target = ((t + GRID - 1u) / GRID) * GRID;
        while (atomicAdd(&g_ctr, 0u) < target) { __nanosleep(64); }
        __threadfence();
    }
    __syncthreads();
}

// ---------------------------------------------------------------------------
// ONE persistent kernel: weight prep -> 4 GEMM stages -> classifier
// 512 threads: warp grid 4(m) x 4(n), warp tile 32x32
// ---------------------------------------------------------------------------
__global__ __launch_bounds__(NTHR, 1)
void mega_kernel(const float* __restrict__ x,
                 const float* __restrict__ enc_w1, const float* __restrict__ enc_b1,
                 const float* __restrict__ enc_w2, const float* __restrict__ enc_b2,
                 const float* __restrict__ gc1_w,  const float* __restrict__ gc1_b,
                 const float* __restrict__ gc2_w,  const float* __restrict__ gc2_b,
                 const float* __restrict__ gc3_w,  const float* __restrict__ gc3_b,
                 const float* __restrict__ cls_w1, const float* __restrict__ cls_b1,
                 const float* __restrict__ cls_w2, const float* __restrict__ cls_b2,
                 float* __restrict__ out)
{
    extern __shared__ float sm[];
    const int tid = threadIdx.x;
    const int wid = tid >> 5, lid = tid & 31;
    const uint32_t smb = smem_u32(sm);
    const uint32_t A0S  = smb + 4096;        // 32KB (128 x 256B)
    const uint32_t A1S  = A0S + 32768;       // 32KB
    const uint32_t BhS  = A1S + 32768;       // 32KB
    const uint32_t BlS  = BhS + 32768;       // 32KB
    const uint32_t rawS = BlS + 32768;       // 33.3KB (130 x 256B)

    // ================= phase 0: weight prep + zero pool =================
    {
        const int gid = blockIdx.x * NTHR + tid;
        if (gid < 4 * 2048) {
            const float* ws[4] = {enc_w2, gc1_w, gc2_w, gc3_w};
            const int layer = gid >> 11, c = gid & 2047;
            const float* w = ws[layer];
            __half* bh = g_Whi[layer];
            __half* bl = g_Wlo[layer];
            const int n = c >> 4, kc = c & 15, k0 = kc * 8;
            const int base = n * 128 + ((kc ^ (n & 7)) << 3);
            #pragma unroll
            for (int j = 0; j < 8; j++) {
                const float v = w[(k0 + j) * DIM + n];
                const __half hi = __float2half_rn(v);
                bh[base + j] = hi;
                bl[base + j] = __float2half_rn((v - __half2float(hi)) * 1024.0f);
            }
        }
        if (gid < NB * DIM) g_part[gid] = 0.f;
    }
    grid_barrier();

    // lane constants
    const int wm = wid & 3, wn = wid >> 2;         // warp grid 4m x 4n
    const int g = lid >> 2, t4 = lid & 3;
    const int arowl = ((lid >> 3) & 1) * 8 + (lid & 7);
    const int akcl  = lid >> 4;
    const int browl = (lid >> 4) * 8 + (lid & 7);
    const int bkcl  = (lid >> 3) & 1;
    const float INV = 1.0f / 1024.0f;
    // gc-build mapping: thread -> 2 rows x 2 chunks (4-row window)
    const int pr = tid >> 3, cp = (tid & 7) * 2;

    // ================= phases 1..4: the four GEMM stages =================
    #pragma unroll 1
    for (int s = 0; s < 4; s++) {
        const int mode = (s == 0) ? 0 : ((s == 3) ? 2 : 1);
        const __half* Whi_g = g_Whi[s];
        const __half* Wlo_g = g_Wlo[s];
        const float* bias = (s == 0) ? enc_b2 : ((s == 1) ? gc1_b : ((s == 2) ? gc2_b : gc3_b));
        const __half* hin = (s == 2) ? g_h1 : g_h0;
        __half* outp = (s == 0) ? g_h0 : ((s == 1) ? g_h1 : ((s == 2) ? g_h0 : g_h1));

        auto issue_raw = [&](int tile) {
            const int tok0 = tile * TOK, s0 = tok0 & (SEQ - 1), bb = tok0 - s0;
            for (int i = tid; i < 130 * 16; i += NTHR) {
                const int row = i >> 4, c = i & 15;
                const int sq = s0 - 1 + row;
                const uint32_t dst = rawS + tswz(row, c);
                if (sq >= 0 && sq < SEQ) cpasync16(dst, hin + (size_t)(bb + sq) * DIM + c * 8);
                else                     sts128(dst, make_uint4(0, 0, 0, 0));
            }
        };
        auto build_A = [&](int tile, uint32_t AS) {
            const int token0 = tile * TOK;
            if (mode != 0) {
                const int s0 = token0 & (SEQ - 1);
                #pragma unroll
                for (int ci = 0; ci < 2; ci++) {
                    const int c = cp + ci;
                    uint4 u[4];
                    #pragma unroll
                    for (int j = 0; j < 4; j++) u[j] = lds128(rawS + tswz(2 * pr + j, c));
                    #pragma unroll
                    for (int k = 0; k < 2; k++) {
                        const int row = 2 * pr + k;
                        const int sq = s0 + row;
                        const float scf = (sq == 0 || sq == SEQ - 1) ? 0.5f : (1.0f / 3.0f);
                        const __half2 sc = __float2half2_rn(scf);
                        uint4 ov;
                        const uint32_t* p0 = &u[k].x;
                        const uint32_t* p1 = &u[k + 1].x;
                        const uint32_t* p2 = &u[k + 2].x;
                        uint32_t* po = &ov.x;
                        #pragma unroll
                        for (int wd = 0; wd < 4; wd++) {
                            __half2 a = *(const __half2*)&p0[wd];
                            __half2 b = *(const __half2*)&p1[wd];
                            __half2 cc = *(const __half2*)&p2[wd];
                            __half2 sv = __hmul2(__hadd2(__hadd2(a, b), cc), sc);
                            po[wd] = *reinterpret_cast<uint32_t*>(&sv);
                        }
                        sts128(AS + tswz(row, c), ov);
                    }
                }
            } else {
                const int r = tid >> 2, q = tid & 3;
                float xv[6];
                const float* xr = x + (size_t)(token0 + r) * 6;
                #pragma unroll
                for (int k = 0; k < 6; k++) xv[k] = xr[k];
                #pragma unroll
                for (int ch = 0; ch < 4; ch++) {
                    const int c = q * 4 + ch;
                    const int k0 = c * 8;
                    uint4 o;
                    uint32_t* po = &o.x;
                    #pragma unroll
                    for (int wd = 0; wd < 4; wd++) {
                        float v0, v1;
                        {
                            const int cc = k0 + wd * 2;
                            float a = sm[896 + cc];
                            #pragma unroll
                            for (int k = 0; k < 6; k++) a += xv[k] * sm[128 + k * 128 + cc];
                            v0 = fmaxf(a, 0.f);
                        }
                        {
                            const int cc = k0 + wd * 2 + 1;
                            float a = sm[896 + cc];
                            #pragma unroll
                            for (int k = 0; k < 6; k++) a += xv[k] * sm[128 + k * 128 + cc];
                            v1 = fmaxf(a, 0.f);
                        }
                        po[wd] = packh(v0, v1);
                    }
                    sts128(AS + tswz(r, c), o);
                }
            }
        };

        // ---- stage prologue: B images + first raw tile + headers ----
        {
            const char* sh = (const char*)Whi_g;
            const char* sl = (const char*)Wlo_g;
            #pragma unroll
            for (int it = 0; it < 4; it++) {
                const int i = tid + it * NTHR;
                cpasync16(BhS + i * 16, sh + i * 16);
                cpasync16(BlS + i * 16, sl + i * 16);
            }
        }
        if (mode != 0) issue_raw(blockIdx.x);
        CP_COMMIT();
        if (tid < 128) sm[tid] = bias[tid];
        if (mode == 0) {
            for (int i = tid; i < 768; i += NTHR) sm[128 + i] = enc_w1[i];
            if (tid < 128) sm[896 + tid] = enc_b1[tid];
        }
        CP_WAIT0();
        __syncthreads();
        build_A(blockIdx.x, A0S);

        int ph = 0;
        for (int tile = blockIdx.x; tile < NTILES; tile += GRID, ph ^= 1) {
            const int token0 = tile * TOK;
            const int tnext = tile + GRID;

            __syncthreads();     // A(tile) visible; raw buffer free of readers

            if (mode != 0 && tnext < NTILES) issue_raw(tnext);
            CP_COMMIT();

            const uint32_t AS = ph ? A1S : A0S;

            // ---- warp-level 2-product GEMM: warp tile 32 x 32 ----
            float acc1[2][4][4], acc2[2][4][4];
            #pragma unroll
            for (int mi = 0; mi < 2; mi++)
                #pragma unroll
                for (int ni = 0; ni < 4; ni++)
                    #pragma unroll
                    for (int j = 0; j < 4; j++) { acc1[mi][ni][j] = 0.f; acc2[mi][ni][j] = 0.f; }

            #pragma unroll
            for (int ks = 0; ks < 8; ks++) {
                uint32_t ah[2][4];
                #pragma unroll
                for (int mi = 0; mi < 2; mi++)
                    LDMX4(ah[mi], AS + tswz(wm * 32 + mi * 16 + arowl, ks * 2 + akcl));
                #pragma unroll
                for (int p = 0; p < 2; p++) {
                    const uint32_t boff = tswz(wn * 32 + p * 16 + browl, ks * 2 + bkcl);
                    uint32_t bh[4], bl[4];
                    LDMX4(bh, BhS + boff);
                    LDMX4(bl, BlS + boff);
                    #pragma unroll
                    for (int hn = 0; hn < 2; hn++) {
                        const int ni = p * 2 + hn;
                        #pragma unroll
                        for (int mi = 0; mi < 2; mi++) {
                            mma16816(acc1[mi][ni], ah[mi], &bh[hn * 2]);
                            mma16816(acc2[mi][ni], ah[mi], &bl[hn * 2]);
                        }
                    }
                }
            }

            // ---- epilogue ----
            if (mode == 2) {
                const int b = token0 >> 11;
                #pragma unroll
                for (int ni = 0; ni < 4; ni++) {
                    const int col = wn * 32 + ni * 8 + 2 * t4;
                    const float bx = sm[col], by = sm[col + 1];
                    float sx = 0.f, sy = 0.f;
                    #pragma unroll
                    for (int mi = 0; mi < 2; mi++) {
                        sx += fmaxf(acc1[mi][ni][0] + acc2[mi][ni][0] * INV + bx, 0.f)
                            + fmaxf(acc1[mi][ni][2] + acc2[mi][ni][2] * INV + bx, 0.f);
                        sy += fmaxf(acc1[mi][ni][1] + acc2[mi][ni][1] * INV + by, 0.f)
                            + fmaxf(acc1[mi][ni][3] + acc2[mi][ni][3] * INV + by, 0.f);
                    }
                    sx += __shfl_xor_sync(0xFFFFFFFFu, sx, 16);
                    sy += __shfl_xor_sync(0xFFFFFFFFu, sy, 16);
                    sx += __shfl_xor_sync(0xFFFFFFFFu, sx, 8);
                    sy += __shfl_xor_sync(0xFFFFFFFFu, sy, 8);
                    sx += __shfl_xor_sync(0xFFFFFFFFu, sx, 4);
                    sy += __shfl_xor_sync(0xFFFFFFFFu, sy, 4);
                    if (g == 0) {
                        atomicAdd(&g_part[b * DIM + col], sx);
                        atomicAdd(&g_part[b * DIM + col + 1], sy);
                    }
                }
            } else {
                const bool relu = (mode == 1);
                #pragma unroll
                for (int mi = 0; mi < 2; mi++) {
                    const int r0 = token0 + wm * 32 + mi * 16 + g;
                    #pragma unroll
                    for (int ni = 0; ni < 4; ni++) {
                        const int col = wn * 32 + ni * 8 + 2 * t4;
                        const float bx = sm[col], by = sm[col + 1];
                        float c0 = acc1[mi][ni][0] + acc2[mi][ni][0] * INV + bx;
                        float c1 = acc1[mi][ni][1] + acc2[mi][ni][1] * INV + by;
                        float c2 = acc1[mi][ni][2] + acc2[mi][ni][2] * INV + bx;
                        float c3 = acc1[mi][ni][3] + acc2[mi][ni][3] * INV + by;
                        if (relu) {
                            c0 = fmaxf(c0, 0.f); c1 = fmaxf(c1, 0.f);
                            c2 = fmaxf(c2, 0.f); c3 = fmaxf(c3, 0.f);
                        }
                        *(__half2*)(outp + (size_t)r0 * DIM + col) = __floats2half2_rn(c0, c1);
                        *(__half2*)(outp + (size_t)(r0 + 8) * DIM + col) = __floats2half2_rn(c2, c3);
                    }
                }
            }

            if (tnext < NTILES) {
                CP_WAIT0();
                build_A(tnext, ph ? A0S : A1S);
            }
        }
        grid_barrier();   // stage complete chip-wide before next stage reads
    }

    // ================= phase 5: classifier (CTAs 0..31) =================
    if (blockIdx.x < NB) {
        const int b = blockIdx.x;
        float* P  = sm;         // reuse smem
        float* C1 = sm + 128;
        if (tid < 128) P[tid] = __ldcg(&g_part[b * DIM + tid]) * (1.0f / (float)SEQ);
        __syncthreads();
        if (tid < 64) {
            float a = cls_b1[tid];
            #pragma unroll 8
            for (int k = 0; k < 128; k++) a += P[k] * cls_w1[k * 64 + tid];
            C1[tid] = fmaxf(a, 0.f);
        }
        __syncthreads();
        if (tid < 3) {
            float a = cls_b2[tid];
            #pragma unroll
            for (int k = 0; k < 64; k++) a += C1[k] * cls_w2[k * 3 + tid];
            out[b * 3 + tid] = a;
        }
    }
}

extern "C" void kernel_launch(void* const* d_in, const int* in_sizes, int n_in,
                              void* d_out, int out_size)
{
    const float* x      = (const float*)d_in[0];
    const float* enc_w1 = (const float*)d_in[1];
    const float* enc_b1 = (const float*)d_in[2];
    const float* enc_w2 = (const float*)d_in[3];
    const float* enc_b2 = (const float*)d_in[4];
    const float* gc1_w  = (const float*)d_in[5];
    const float* gc1_b  = (const float*)d_in[6];
    const float* gc2_w  = (const float*)d_in[7];
    const float* gc2_b  = (const float*)d_in[8];
    const float* gc3_w  = (const float*)d_in[9];
    const float* gc3_b  = (const float*)d_in[10];
    const float* cls_w1 = (const float*)d_in[11];
    const float* cls_b1 = (const float*)d_in[12];
    const float* cls_w2 = (const float*)d_in[13];
    const float* cls_b2 = (const float*)d_in[14];
    float* out = (float*)d_out;

    const size_t mega_sm = 4096 + 32768 * 4 + 130 * 256;  // 168448 B
    cudaFuncSetAttribute(mega_kernel, cudaFuncAttributeMaxDynamicSharedMemorySize, (int)mega_sm);
    cudaFuncSetAttribute(mega_kernel, cudaFuncAttributePreferredSharedMemoryCarveout, 100);

    mega_kernel<<<GRID, NTHR, mega_sm>>>(x, enc_w1, enc_b1, enc_w2, enc_b2,
                                         gc1_w, gc1_b, gc2_w, gc2_b, gc3_w, gc3_b,
                                         cls_w1, cls_b1, cls_w2, cls_b2, out);
}

// round 15
// speedup vs baseline: 1.5133x; 1.5133x over previous
#include <cuda_runtime.h>
#include <cuda_fp16.h>
#include <cstdint>

#define SEQ 2048
#define NB  32
#define DIM 128
#define NTOK (NB*SEQ)
#define TOK 128
#define NTILES (NTOK/TOK)      // 512
#define GRID 296               // 2 CTAs/SM, all co-resident
#define NTHR 256

// ---------------- scratch (no allocations allowed) ----------------
__device__ __align__(16) __half g_h0[NTOK*DIM];
__device__ __align__(16) __half g_h1[NTOK*DIM];
__device__ float g_part[NB*DIM];
__device__ __align__(16) __half g_Whi[4][DIM*DIM];
__device__ unsigned g_ctr;     // monotonic grid-barrier counter (replay-safe)

// ---------------- helpers ----------------
__device__ __forceinline__ uint32_t smem_u32(const void* p) {
    uint32_t a;
    asm("{ .reg .u64 t; cvta.to.shared.u64 t, %1; cvt.u32.u64 %0, t; }" : "=r"(a) : "l"(p));
    return a;
}
__device__ __forceinline__ void sts128(uint32_t addr, uint4 v) {
    asm volatile("st.shared.v4.b32 [%0], {%1,%2,%3,%4};" :: "r"(addr), "r"(v.x), "r"(v.y), "r"(v.z), "r"(v.w) : "memory");
}
__device__ __forceinline__ uint4 lds128(uint32_t addr) {
    uint4 v;
    asm volatile("ld.shared.v4.b32 {%0,%1,%2,%3}, [%4];"
        : "=r"(v.x), "=r"(v.y), "=r"(v.z), "=r"(v.w) : "r"(addr));
    return v;
}
__device__ __forceinline__ void cpasync16(uint32_t dst, const void* src) {
    asm volatile("cp.async.cg.shared.global [%0], [%1], 16;" :: "r"(dst), "l"(src) : "memory");
}
#define CP_COMMIT() asm volatile("cp.async.commit_group;" ::: "memory")
#define CP_WAIT0()  asm volatile("cp.async.wait_group 0;" ::: "memory")
#define LDMX4(r, addr) \
    asm volatile("ldmatrix.sync.aligned.m8n8.x4.shared.b16 {%0,%1,%2,%3}, [%4];" \
        : "=r"((r)[0]), "=r"((r)[1]), "=r"((r)[2]), "=r"((r)[3]) : "r"(addr))
__device__ __forceinline__ void mma16816(float* d, const uint32_t* a, const uint32_t* b) {
    asm volatile(
        "mma.sync.aligned.m16n8k16.row.col.f32.f16.f16.f32 "
        "{%0,%1,%2,%3}, {%4,%5,%6,%7}, {%8,%9}, {%0,%1,%2,%3};"
        : "+f"(d[0]), "+f"(d[1]), "+f"(d[2]), "+f"(d[3])
        : "r"(a[0]), "r"(a[1]), "r"(a[2]), "r"(a[3]), "r"(b[0]), "r"(b[1]));
}
__device__ __forceinline__ uint32_t tswz(int row, int kchunk) {
    return (uint32_t)(row * 256 + ((kchunk ^ (row & 7)) << 4));
}
__device__ __forceinline__ uint32_t packh(float a, float b) {
    __half2 t = __floats2half2_rn(a, b);
    return *reinterpret_cast<uint32_t*>(&t);
}

// replay-safe grid barrier: monotonic counter, release->acquire via threadfence
__device__ __forceinline__ void grid_barrier() {
    __syncthreads();
    if (threadIdx.x == 0) {
        __threadfence();
        const unsigned t = atomicAdd(&g_ctr, 1u) + 1u;
        const unsigned target = ((t + GRID - 1u) / GRID) * GRID;
        while (atomicAdd(&g_ctr, 0u) < target) { __nanosleep(64); }
        __threadfence();
    }
    __syncthreads();
}

// ---------------------------------------------------------------------------
// ONE persistent kernel: weight prep -> 4 GEMM stages -> classifier
// 256 threads, 2 CTAs/SM. Single-product fp16 GEMM; warp tile 64x32.
// ---------------------------------------------------------------------------
__global__ __launch_bounds__(NTHR, 2)
void mega_kernel(const float* __restrict__ x,
                 const float* __restrict__ enc_w1, const float* __restrict__ enc_b1,
                 const float* __restrict__ enc_w2, const float* __restrict__ enc_b2,
                 const float* __restrict__ gc1_w,  const float* __restrict__ gc1_b,
                 const float* __restrict__ gc2_w,  const float* __restrict__ gc2_b,
                 const float* __restrict__ gc3_w,  const float* __restrict__ gc3_b,
                 const float* __restrict__ cls_w1, const float* __restrict__ cls_b1,
                 const float* __restrict__ cls_w2, const float* __restrict__ cls_b2,
                 float* __restrict__ out)
{
    extern __shared__ float sm[];
    const int tid = threadIdx.x;
    const int wid = tid >> 5, lid = tid & 31;
    const uint32_t smb = smem_u32(sm);
    const uint32_t AS   = smb + 4096;        // 32KB (128 x 256B)
    const uint32_t BhS  = AS + 32768;        // 32KB
    const uint32_t rawS = BhS + 32768;       // 33.3KB (130 x 256B)

    // ================= phase 0: weight prep + zero pool =================
    {
        const int gid = blockIdx.x * NTHR + tid;
        if (gid < 4 * 2048) {
            const float* ws[4] = {enc_w2, gc1_w, gc2_w, gc3_w};
            const int layer = gid >> 11, c = gid & 2047;
            const float* w = ws[layer];
            __half* bh = g_Whi[layer];
            const int n = c >> 4, kc = c & 15, k0 = kc * 8;
            const int base = n * 128 + ((kc ^ (n & 7)) << 3);
            #pragma unroll
            for (int j = 0; j < 8; j++)
                bh[base + j] = __float2half_rn(w[(k0 + j) * DIM + n]);
        }
        if (gid < NB * DIM) g_part[gid] = 0.f;
    }
    grid_barrier();

    // lane constants: warp grid 2(m) x 4(n), warp tile 64 x 32
    const int wm = wid & 1, wn = wid >> 1;
    const int g = lid >> 2, t4 = lid & 3;
    const int arowl = ((lid >> 3) & 1) * 8 + (lid & 7);
    const int akcl  = lid >> 4;
    const int browl = (lid >> 4) * 8 + (lid & 7);
    const int bkcl  = (lid >> 3) & 1;

    // ================= phases 1..4: the four GEMM stages =================
    #pragma unroll 1
    for (int s = 0; s < 4; s++) {
        const int mode = (s == 0) ? 0 : ((s == 3) ? 2 : 1);
        const __half* Whi_g = g_Whi[s];
        const float* bias = (s == 0) ? enc_b2 : ((s == 1) ? gc1_b : ((s == 2) ? gc2_b : gc3_b));
        const __half* hin = (s == 2) ? g_h1 : g_h0;
        __half* outp = (s == 0) ? g_h0 : ((s == 1) ? g_h1 : ((s == 2) ? g_h0 : g_h1));

        auto issue_raw = [&](int tile) {
            const int tok0 = tile * TOK, s0 = tok0 & (SEQ - 1), bb = tok0 - s0;
            for (int i = tid; i < 130 * 16; i += NTHR) {
                const int row = i >> 4, c = i & 15;
                const int sq = s0 - 1 + row;
                const uint32_t dst = rawS + tswz(row, c);
                if (sq >= 0 && sq < SEQ) cpasync16(dst, hin + (size_t)(bb + sq) * DIM + c * 8);
                else                     sts128(dst, make_uint4(0, 0, 0, 0));
            }
        };
        auto build_A = [&](int tile) {
            const int token0 = tile * TOK;
            if (mode != 0) {
                const int s0 = token0 & (SEQ - 1);
                const int r = tid >> 1, q = tid & 1;
                const int sq = s0 + r;
                const float scf = (sq == 0 || sq == SEQ - 1) ? 0.5f : (1.0f / 3.0f);
                const __half2 sc = __float2half2_rn(scf);
                #pragma unroll
                for (int ch = 0; ch < 8; ch++) {
                    const int c = q * 8 + ch;
                    const uint4 u0 = lds128(rawS + tswz(r,     c));
                    const uint4 u1 = lds128(rawS + tswz(r + 1, c));
                    const uint4 u2 = lds128(rawS + tswz(r + 2, c));
                    uint4 ov;
                    const uint32_t* p0 = &u0.x;
                    const uint32_t* p1 = &u1.x;
                    const uint32_t* p2 = &u2.x;
                    uint32_t* po = &ov.x;
                    #pragma unroll
                    for (int wd = 0; wd < 4; wd++) {
                        __half2 a = *(const __half2*)&p0[wd];
                        __half2 b = *(const __half2*)&p1[wd];
                        __half2 cc = *(const __half2*)&p2[wd];
                        __half2 sv = __hmul2(__hadd2(__hadd2(a, b), cc), sc);
                        po[wd] = *reinterpret_cast<uint32_t*>(&sv);
                    }
                    sts128(AS + tswz(r, c), ov);
                }
            } else {
                const int r = tid >> 1, q = tid & 1;
                float xv[6];
                const float* xr = x + (size_t)(token0 + r) * 6;
                #pragma unroll
                for (int k = 0; k < 6; k++) xv[k] = xr[k];
                #pragma unroll
                for (int ch = 0; ch < 8; ch++) {
                    const int c = q * 8 + ch;
                    const int k0 = c * 8;
                    uint4 o;
                    uint32_t* po = &o.x;
                    #pragma unroll
                    for (int wd = 0; wd < 4; wd++) {
                        float v0, v1;
                        {
                            const int cc = k0 + wd * 2;
                            float a = sm[896 + cc];
                            #pragma unroll
                            for (int k = 0; k < 6; k++) a += xv[k] * sm[128 + k * 128 + cc];
                            v0 = fmaxf(a, 0.f);
                        }
                        {
                            const int cc = k0 + wd * 2 + 1;
                            float a = sm[896 + cc];
                            #pragma unroll
                            for (int k = 0; k < 6; k++) a += xv[k] * sm[128 + k * 128 + cc];
                            v1 = fmaxf(a, 0.f);
                        }
                        po[wd] = packh(v0, v1);
                    }
                    sts128(AS + tswz(r, c), o);
                }
            }
        };

        // ---- stage prologue: B image + first raw tile + headers ----
        {
            const char* sh = (const char*)Whi_g;
            #pragma unroll
            for (int it = 0; it < 8; it++) {
                const int i = tid + it * NTHR;
                cpasync16(BhS + i * 16, sh + i * 16);
            }
        }
        if (mode != 0) issue_raw(blockIdx.x);
        CP_COMMIT();
        if (tid < 128) sm[tid] = bias[tid];
        if (mode == 0) {
            for (int i = tid; i < 768; i += NTHR) sm[128 + i] = enc_w1[i];
            if (tid < 128) sm[896 + tid] = enc_b1[tid];
        }
        CP_WAIT0();
        __syncthreads();

        for (int tile = blockIdx.x; tile < NTILES; tile += GRID) {
            const int token0 = tile * TOK;
            const int tnext = tile + GRID;

            build_A(tile);
            __syncthreads();     // A built; raw buffer free of readers

            if (mode != 0 && tnext < NTILES) issue_raw(tnext);
            CP_COMMIT();

            // ---- warp-level single-product GEMM: warp tile 64 x 32 ----
            float acc[4][4][4];
            #pragma unroll
            for (int mi = 0; mi < 4; mi++)
                #pragma unroll
                for (int ni = 0; ni < 4; ni++)
                    #pragma unroll
                    for (int j = 0; j < 4; j++) acc[mi][ni][j] = 0.f;

            #pragma unroll
            for (int ks = 0; ks < 8; ks++) {
                uint32_t ah[4][4];
                #pragma unroll
                for (int mi = 0; mi < 4; mi++)
                    LDMX4(ah[mi], AS + tswz(wm * 64 + mi * 16 + arowl, ks * 2 + akcl));
                #pragma unroll
                for (int p = 0; p < 2; p++) {
                    uint32_t bf[4];
                    LDMX4(bf, BhS + tswz(wn * 32 + p * 16 + browl, ks * 2 + bkcl));
                    #pragma unroll
                    for (int hn = 0; hn < 2; hn++)
                        #pragma unroll
                        for (int mi = 0; mi < 4; mi++)
                            mma16816(acc[mi][p * 2 + hn], ah[mi], &bf[hn * 2]);
                }
            }

            // ---- epilogue ----
            if (mode == 2) {
                const int b = token0 >> 11;
                #pragma unroll
                for (int ni = 0; ni < 4; ni++) {
                    const int col = wn * 32 + ni * 8 + 2 * t4;
                    const float bx = sm[col], by = sm[col + 1];
                    float sx = 0.f, sy = 0.f;
                    #pragma unroll
                    for (int mi = 0; mi < 4; mi++) {
                        sx += fmaxf(acc[mi][ni][0] + bx, 0.f) + fmaxf(acc[mi][ni][2] + bx, 0.f);
                        sy += fmaxf(acc[mi][ni][1] + by, 0.f) + fmaxf(acc[mi][ni][3] + by, 0.f);
                    }
                    sx += __shfl_xor_sync(0xFFFFFFFFu, sx, 16);
                    sy += __shfl_xor_sync(0xFFFFFFFFu, sy, 16);
                    sx += __shfl_xor_sync(0xFFFFFFFFu, sx, 8);
                    sy += __shfl_xor_sync(0xFFFFFFFFu, sy, 8);
                    sx += __shfl_xor_sync(0xFFFFFFFFu, sx, 4);
                    sy += __shfl_xor_sync(0xFFFFFFFFu, sy, 4);
                    if (g == 0) {
                        atomicAdd(&g_part[b * DIM + col], sx);
                        atomicAdd(&g_part[b * DIM + col + 1], sy);
                    }
                }
            } else {
                const bool relu = (mode == 1);
                #pragma unroll
                for (int mi = 0; mi < 4; mi++) {
                    const int r0 = token0 + wm * 64 + mi * 16 + g;
                    #pragma unroll
                    for (int ni = 0; ni < 4; ni++) {
                        const int col = wn * 32 + ni * 8 + 2 * t4;
                        const float bx = sm[col], by = sm[col + 1];
                        float c0 = acc[mi][ni][0] + bx;
                        float c1 = acc[mi][ni][1] + by;
                        float c2 = acc[mi][ni][2] + bx;
                        float c3 = acc[mi][ni][3] + by;
                        if (relu) {
                            c0 = fmaxf(c0, 0.f); c1 = fmaxf(c1, 0.f);
                            c2 = fmaxf(c2, 0.f); c3 = fmaxf(c3, 0.f);
                        }
                        *(__half2*)(outp + (size_t)r0 * DIM + col) = __floats2half2_rn(c0, c1);
                        *(__half2*)(outp + (size_t)(r0 + 8) * DIM + col) = __floats2half2_rn(c2, c3);
                    }
                }
            }

            CP_WAIT0();          // next raw tile landed
            __syncthreads();     // A readers done before next build
        }
        grid_barrier();   // stage complete chip-wide before next stage reads
    }

    // ================= phase 5: classifier (CTAs 0..31) =================
    if (blockIdx.x < NB) {
        const int b = blockIdx.x;
        float* P  = sm;
        float* C1 = sm + 128;
        if (tid < 128) P[tid] = __ldcg(&g_part[b * DIM + tid]) * (1.0f / (float)SEQ);
        __syncthreads();
        if (tid < 64) {
            float a = cls_b1[tid];
            #pragma unroll 8
            for (int k = 0; k < 128; k++) a += P[k] * cls_w1[k * 64 + tid];
            C1[tid] = fmaxf(a, 0.f);
        }
        __syncthreads();
        if (tid < 3) {
            float a = cls_b2[tid];
            #pragma unroll
            for (int k = 0; k < 64; k++) a += C1[k] * cls_w2[k * 3 + tid];
            out[b * 3 + tid] = a;
        }
    }
}

extern "C" void kernel_launch(void* const* d_in, const int* in_sizes, int n_in,
                              void* d_out, int out_size)
{
    const float* x      = (const float*)d_in[0];
    const float* enc_w1 = (const float*)d_in[1];
    const float* enc_b1 = (const float*)d_in[2];
    const float* enc_w2 = (const float*)d_in[3];
    const float* enc_b2 = (const float*)d_in[4];
    const float* gc1_w  = (const float*)d_in[5];
    const float* gc1_b  = (const float*)d_in[6];
    const float* gc2_w  = (const float*)d_in[7];
    const float* gc2_b  = (const float*)d_in[8];
    const float* gc3_w  = (const float*)d_in[9];
    const float* gc3_b  = (const float*)d_in[10];
    const float* cls_w1 = (const float*)d_in[11];
    const float* cls_b1 = (const float*)d_in[12];
    const float* cls_w2 = (const float*)d_in[13];
    const float* cls_b2 = (const float*)d_in[14];
    float* out = (float*)d_out;

    const size_t mega_sm = 4096 + 32768 * 2 + 130 * 256;  // 103168 B -> 2 CTAs/SM
    cudaFuncSetAttribute(mega_kernel, cudaFuncAttributeMaxDynamicSharedMemorySize, (int)mega_sm);
    cudaFuncSetAttribute(mega_kernel, cudaFuncAttributePreferredSharedMemoryCarveout, 100);

    mega_kernel<<<GRID, NTHR, mega_sm>>>(x, enc_w1, enc_b1, enc_w2, enc_b2,
                                         gc1_w, gc1_b, gc2_w, gc2_b, gc3_w, gc3_b,
                                         cls_w1, cls_b1, cls_w2, cls_b2, out);
}

// round 16
// speedup vs baseline: 1.7385x; 1.1488x over previous
#include <cuda_runtime.h>
#include <cuda_fp16.h>
#include <cstdint>

#define SEQ 2048
#define NB  32
#define DIM 128
#define NTOK (NB*SEQ)
#define TOK 128
#define NTILES (NTOK/TOK)      // 512
#define GRID 296               // 2 CTAs/SM, all co-resident
#define NTHR 256
#define MROWS 144              // 128 tokens + 8-row halo each side
#define OFF 8                  // buffer row i <-> seq s0-8+i

// ---------------- scratch (no allocations allowed) ----------------
__device__ float g_part[NB*DIM];
__device__ __align__(16) __half g_Whi[4][DIM*DIM];
__device__ unsigned g_ctr;     // monotonic grid-barrier counter (replay-safe)

// ---------------- helpers ----------------
__device__ __forceinline__ uint32_t smem_u32(const void* p) {
    uint32_t a;
    asm("{ .reg .u64 t; cvta.to.shared.u64 t, %1; cvt.u32.u64 %0, t; }" : "=r"(a) : "l"(p));
    return a;
}
__device__ __forceinline__ void sts128(uint32_t addr, uint4 v) {
    asm volatile("st.shared.v4.b32 [%0], {%1,%2,%3,%4};" :: "r"(addr), "r"(v.x), "r"(v.y), "r"(v.z), "r"(v.w) : "memory");
}
__device__ __forceinline__ void sts32(uint32_t addr, uint32_t v) {
    asm volatile("st.shared.b32 [%0], %1;" :: "r"(addr), "r"(v) : "memory");
}
__device__ __forceinline__ uint4 lds128(uint32_t addr) {
    uint4 v;
    asm volatile("ld.shared.v4.b32 {%0,%1,%2,%3}, [%4];"
        : "=r"(v.x), "=r"(v.y), "=r"(v.z), "=r"(v.w) : "r"(addr));
    return v;
}
__device__ __forceinline__ void cpasync16(uint32_t dst, const void* src) {
    asm volatile("cp.async.cg.shared.global [%0], [%1], 16;" :: "r"(dst), "l"(src) : "memory");
}
#define CP_COMMIT() asm volatile("cp.async.commit_group;" ::: "memory")
#define CP_WAIT0()  asm volatile("cp.async.wait_group 0;" ::: "memory")
#define LDMX4(r, addr) \
    asm volatile("ldmatrix.sync.aligned.m8n8.x4.shared.b16 {%0,%1,%2,%3}, [%4];" \
        : "=r"((r)[0]), "=r"((r)[1]), "=r"((r)[2]), "=r"((r)[3]) : "r"(addr))
__device__ __forceinline__ void mma16816(float* d, const uint32_t* a, const uint32_t* b) {
    asm volatile(
        "mma.sync.aligned.m16n8k16.row.col.f32.f16.f16.f32 "
        "{%0,%1,%2,%3}, {%4,%5,%6,%7}, {%8,%9}, {%0,%1,%2,%3};"
        : "+f"(d[0]), "+f"(d[1]), "+f"(d[2]), "+f"(d[3])
        : "r"(a[0]), "r"(a[1]), "r"(a[2]), "r"(a[3]), "r"(b[0]), "r"(b[1]));
}
__device__ __forceinline__ uint32_t tswz(int row, int kchunk) {
    return (uint32_t)(row * 256 + ((kchunk ^ (row & 7)) << 4));
}
__device__ __forceinline__ uint32_t packh(float a, float b) {
    __half2 t = __floats2half2_rn(a, b);
    return *reinterpret_cast<uint32_t*>(&t);
}

// replay-safe grid barrier
__device__ __forceinline__ void grid_barrier() {
    __syncthreads();
    if (threadIdx.x == 0) {
        __threadfence();
        const unsigned t = atomicAdd(&g_ctr, 1u) + 1u;
        const unsigned target = ((t + GRID - 1u) / GRID) * GRID;
        while (atomicAdd(&g_ctr, 0u) < target) { __nanosleep(64); }
        __threadfence();
    }
    __syncthreads();
}

// ---------------------------------------------------------------------------
// ONE persistent kernel: all 4 layers fused per tile in smem, then classifier.
// 256 threads, 2 CTAs/SM. Warp grid 2m x 4n; wm=0 owns m-frags 0..4, wm=1 5..8.
// ---------------------------------------------------------------------------
__global__ __launch_bounds__(NTHR, 2)
void mega_kernel(const float* __restrict__ x,
                 const float* __restrict__ enc_w1, const float* __restrict__ enc_b1,
                 const float* __restrict__ enc_w2, const float* __restrict__ enc_b2,
                 const float* __restrict__ gc1_w,  const float* __restrict__ gc1_b,
                 const float* __restrict__ gc2_w,  const float* __restrict__ gc2_b,
                 const float* __restrict__ gc3_w,  const float* __restrict__ gc3_b,
                 const float* __restrict__ cls_w1, const float* __restrict__ cls_b1,
                 const float* __restrict__ cls_w2, const float* __restrict__ cls_b2,
                 float* __restrict__ out)
{
    extern __shared__ float sm[];
    const int tid = threadIdx.x;
    const int wid = tid >> 5, lid = tid & 31;
    const uint32_t smb = smem_u32(sm);
    const uint32_t A0S = smb + 6144;        // 36KB (144 x 256B): h buffer
    const uint32_t A1S = A0S + 36864;       // 36KB: MMA-input buffer
    const uint32_t BS  = A1S + 36864;       // 32KB: weight image

    // ================= phase 0: weight prep + zero pool + headers =================
    {
        const int gid = blockIdx.x * NTHR + tid;
        if (gid < 4 * 2048) {
            const float* ws[4] = {enc_w2, gc1_w, gc2_w, gc3_w};
            const int layer = gid >> 11, c = gid & 2047;
            const float* w = ws[layer];
            __half* bh = g_Whi[layer];
            const int n = c >> 4, kc = c & 15, k0 = kc * 8;
            const int base = n * 128 + ((kc ^ (n & 7)) << 3);
            #pragma unroll
            for (int j = 0; j < 8; j++)
                bh[base + j] = __float2half_rn(w[(k0 + j) * DIM + n]);
        }
        if (gid < NB * DIM) g_part[gid] = 0.f;
    }
    // smem header: bias[4][128] @0, w1 @512, b1 @1280
    if (tid < 128) {
        sm[tid]       = enc_b2[tid];
        sm[128 + tid] = gc1_b[tid];
        sm[256 + tid] = gc2_b[tid];
        sm[384 + tid] = gc3_b[tid];
        sm[1280 + tid] = enc_b1[tid];
    }
    for (int i = tid; i < 768; i += NTHR) sm[512 + i] = enc_w1[i];
    grid_barrier();

    // lane constants
    const int wm = wid & 1, wn = wid >> 1;
    const int g = lid >> 2, t4 = lid & 3;
    const int arowl = ((lid >> 3) & 1) * 8 + (lid & 7);
    const int akcl  = lid >> 4;
    const int browl = (lid >> 4) * 8 + (lid & 7);
    const int bkcl  = (lid >> 3) & 1;
    const int mf0 = wm ? 5 : 0;
    const int NM  = wm ? 4 : 5;
    const int r2 = tid >> 1, q = tid & 1;     // build/agg: 2 threads/row

    // ================= tile loop: all 4 layers fused =================
    for (int tile = blockIdx.x; tile < NTILES; tile += GRID) {
        const int token0 = tile * TOK;
        const int s0 = token0 & (SEQ - 1);
        const int bb = token0 - s0;

        // ---- issue B0 (enc_w2 image) ----
        {
            const char* sh = (const char*)g_Whi[0];
            #pragma unroll
            for (int it = 0; it < 8; it++) {
                const int i = tid + it * NTHR;
                cpasync16(BS + i * 16, sh + i * 16);
            }
            CP_COMMIT();
        }

        // ---- enc layer-1 build into A1: h1 = relu(x@w1+b1), 144 rows ----
        for (int rr = r2; rr < MROWS; rr += 128) {
            const int s = s0 - OFF + rr;
            if (s >= 0 && s < SEQ) {
                float xv[6];
                const float* xr = x + (size_t)(bb + s) * 6;
                #pragma unroll
                for (int k = 0; k < 6; k++) xv[k] = xr[k];
                #pragma unroll
                for (int ch = 0; ch < 8; ch++) {
                    const int c = q * 8 + ch;
                    const int k0 = c * 8;
                    uint4 o;
                    uint32_t* po = &o.x;
                    #pragma unroll
                    for (int wd = 0; wd < 4; wd++) {
                        float v0, v1;
                        {
                            const int cc = k0 + wd * 2;
                            float a = sm[1280 + cc];
                            #pragma unroll
                            for (int k = 0; k < 6; k++) a += xv[k] * sm[512 + k * 128 + cc];
                            v0 = fmaxf(a, 0.f);
                        }
                        {
                            const int cc = k0 + wd * 2 + 1;
                            float a = sm[1280 + cc];
                            #pragma unroll
                            for (int k = 0; k < 6; k++) a += xv[k] * sm[512 + k * 128 + cc];
                            v1 = fmaxf(a, 0.f);
                        }
                        po[wd] = packh(v0, v1);
                    }
                    sts128(A1S + tswz(rr, c), o);
                }
            } else {
                #pragma unroll
                for (int ch = 0; ch < 8; ch++)
                    sts128(A1S + tswz(rr, q * 8 + ch), make_uint4(0, 0, 0, 0));
            }
        }
        CP_WAIT0();
        __syncthreads();

        // ---- 4 layers ----
        #pragma unroll 1
        for (int k = 0; k < 4; k++) {
            // agg pass for gc layers: A0 (h) -> A1 (agg'd, scaled, OOB-zeroed)
            if (k > 0) {
                for (int rr = r2; rr < MROWS; rr += 128) {
                    const int s = s0 - OFF + rr;
                    if (s >= 0 && s < SEQ) {
                        const float scf = (s == 0 || s == SEQ - 1) ? 0.5f : (1.0f / 3.0f);
                        const __half2 sc = __float2half2_rn(scf);
                        const int rm = (rr > 0) ? rr - 1 : 0;
                        const int rp = (rr < MROWS - 1) ? rr + 1 : MROWS - 1;
                        #pragma unroll
                        for (int ch = 0; ch < 8; ch++) {
                            const int c = q * 8 + ch;
                            const uint4 u0 = lds128(A0S + tswz(rm, c));
                            const uint4 u1 = lds128(A0S + tswz(rr, c));
                            const uint4 u2 = lds128(A0S + tswz(rp, c));
                            uint4 ov;
                            const uint32_t* p0 = &u0.x;
                            const uint32_t* p1 = &u1.x;
                            const uint32_t* p2 = &u2.x;
                            uint32_t* po = &ov.x;
                            #pragma unroll
                            for (int wd = 0; wd < 4; wd++) {
                                __half2 a = *(const __half2*)&p0[wd];
                                __half2 b = *(const __half2*)&p1[wd];
                                __half2 cc = *(const __half2*)&p2[wd];
                                __half2 sv = __hmul2(__hadd2(__hadd2(a, b), cc), sc);
                                po[wd] = *reinterpret_cast<uint32_t*>(&sv);
                            }
                            sts128(A1S + tswz(rr, c), ov);
                        }
                    } else {
                        #pragma unroll
                        for (int ch = 0; ch < 8; ch++)
                            sts128(A1S + tswz(rr, q * 8 + ch), make_uint4(0, 0, 0, 0));
                    }
                }
                __syncthreads();
            }

            // ---- GEMM: A1[144x128] x B -> acc ----
            float acc[5][4][4];
            #pragma unroll
            for (int mi = 0; mi < 5; mi++)
                #pragma unroll
                for (int ni = 0; ni < 4; ni++)
                    #pragma unroll
                    for (int j = 0; j < 4; j++) acc[mi][ni][j] = 0.f;

            #pragma unroll
            for (int ks = 0; ks < 8; ks++) {
                uint32_t ah[5][4];
                #pragma unroll
                for (int mi = 0; mi < 5; mi++)
                    if (mi < NM)
                        LDMX4(ah[mi], A1S + tswz((mf0 + mi) * 16 + arowl, ks * 2 + akcl));
                #pragma unroll
                for (int p = 0; p < 2; p++) {
                    uint32_t bf[4];
                    LDMX4(bf, BS + tswz(wn * 32 + p * 16 + browl, ks * 2 + bkcl));
                    #pragma unroll
                    for (int hn = 0; hn < 2; hn++)
                        #pragma unroll
                        for (int mi = 0; mi < 5; mi++)
                            if (mi < NM)
                                mma16816(acc[mi][p * 2 + hn], ah[mi], &bf[hn * 2]);
                }
            }
            __syncthreads();   // B consumed by all warps

            // ---- prefetch next layer's B during epilogue ----
            if (k < 3) {
                const char* sh = (const char*)g_Whi[k + 1];
                #pragma unroll
                for (int it = 0; it < 8; it++) {
                    const int i = tid + it * NTHR;
                    cpasync16(BS + i * 16, sh + i * 16);
                }
            }
            CP_COMMIT();

            // ---- epilogue ----
            if (k == 3) {
                // fused mean-pool: rows 8..135 only
                const int b = token0 >> 11;
                #pragma unroll
                for (int ni = 0; ni < 4; ni++) {
                    const int col = wn * 32 + ni * 8 + 2 * t4;
                    const float bx = sm[384 + col], by = sm[384 + col + 1];
                    float sx = 0.f, sy = 0.f;
                    #pragma unroll
                    for (int mi = 0; mi < 5; mi++) {
                        if (mi < NM) {
                            const int r0 = (mf0 + mi) * 16 + g;
                            if (r0 >= OFF && r0 < OFF + TOK) {
                                sx += fmaxf(acc[mi][ni][0] + bx, 0.f);
                                sy += fmaxf(acc[mi][ni][1] + by, 0.f);
                            }
                            if (r0 + 8 >= OFF && r0 + 8 < OFF + TOK) {
                                sx += fmaxf(acc[mi][ni][2] + bx, 0.f);
                                sy += fmaxf(acc[mi][ni][3] + by, 0.f);
                            }
                        }
                    }
                    sx += __shfl_xor_sync(0xFFFFFFFFu, sx, 16);
                    sy += __shfl_xor_sync(0xFFFFFFFFu, sy, 16);
                    sx += __shfl_xor_sync(0xFFFFFFFFu, sx, 8);
                    sy += __shfl_xor_sync(0xFFFFFFFFu, sy, 8);
                    sx += __shfl_xor_sync(0xFFFFFFFFu, sx, 4);
                    sy += __shfl_xor_sync(0xFFFFFFFFu, sy, 4);
                    if (g == 0) {
                        atomicAdd(&g_part[b * DIM + col], sx);
                        atomicAdd(&g_part[b * DIM + col + 1], sy);
                    }
                }
            } else {
                // write h = relu(acc + bias) into A0 (OOB rows -> 0)
                #pragma unroll
                for (int mi = 0; mi < 5; mi++) {
                    if (mi < NM) {
                        const int r0 = (mf0 + mi) * 16 + g;
                        const int sA = s0 - OFF + r0;
                        const int sB = sA + 8;
                        const bool vA = (k == 0) ? ((unsigned)sA < SEQ) : ((unsigned)sA < SEQ);
                        const bool vB = ((unsigned)sB < SEQ);
                        #pragma unroll
                        for (int ni = 0; ni < 4; ni++) {
                            const int col = wn * 32 + ni * 8 + 2 * t4;
                            const float bx = sm[k * 128 + col], by = sm[k * 128 + col + 1];
                            uint32_t w0 = 0, w1 = 0;
                            if (vA) {
                                float c0 = acc[mi][ni][0] + bx, c1 = acc[mi][ni][1] + by;
                                if (k > 0) { c0 = fmaxf(c0, 0.f); c1 = fmaxf(c1, 0.f); }
                                w0 = packh(c0, c1);
                            }
                            if (vB) {
                                float c2 = acc[mi][ni][2] + bx, c3 = acc[mi][ni][3] + by;
                                if (k > 0) { c2 = fmaxf(c2, 0.f); c3 = fmaxf(c3, 0.f); }
                                w1 = packh(c2, c3);
                            }
                            const uint32_t chunk = (uint32_t)(wn * 4 + ni);
                            sts32(A0S + tswz(r0, chunk) + t4 * 4, w0);
                            sts32(A0S + tswz(r0 + 8, chunk) + t4 * 4, w1);
                        }
                    }
                }
            }
            CP_WAIT0();
            __syncthreads();
        }
    }

    grid_barrier();

    // ================= classifier (CTAs 0..31) =================
    if (blockIdx.x < NB) {
        const int b = blockIdx.x;
        float* P  = sm + 1536;
        float* C1 = sm + 1664;
        if (tid < 128) P[tid] = __ldcg(&g_part[b * DIM + tid]) * (1.0f / (float)SEQ);
        __syncthreads();
        if (tid < 64) {
            float a = cls_b1[tid];
            #pragma unroll 8
            for (int k = 0; k < 128; k++) a += P[k] * cls_w1[k * 64 + tid];
            C1[tid] = fmaxf(a, 0.f);
        }
        __syncthreads();
        if (tid < 3) {
            float a = cls_b2[tid];
            #pragma unroll
            for (int k = 0; k < 64; k++) a += C1[k] * cls_w2[k * 3 + tid];
            out[b * 3 + tid] = a;
        }
    }
}

extern "C" void kernel_launch(void* const* d_in, const int* in_sizes, int n_in,
                              void* d_out, int out_size)
{
    const float* x      = (const float*)d_in[0];
    const float* enc_w1 = (const float*)d_in[1];
    const float* enc_b1 = (const float*)d_in[2];
    const float* enc_w2 = (const float*)d_in[3];
    const float* enc_b2 = (const float*)d_in[4];
    const float* gc1_w  = (const float*)d_in[5];
    const float* gc1_b  = (const float*)d_in[6];
    const float* gc2_w  = (const float*)d_in[7];
    const float* gc2_b  = (const float*)d_in[8];
    const float* gc3_w  = (const float*)d_in[9];
    const float* gc3_b  = (const float*)d_in[10];
    const float* cls_w1 = (const float*)d_in[11];
    const float* cls_b1 = (const float*)d_in[12];
    const float* cls_w2 = (const float*)d_in[13];
    const float* cls_b2 = (const float*)d_in[14];
    float* out = (float*)d_out;

    const size_t mega_sm = 6144 + 36864 * 2 + 32768;  // 112640 B -> 2 CTAs/SM
    cudaFuncSetAttribute(mega_kernel, cudaFuncAttributeMaxDynamicSharedMemorySize, (int)mega_sm);
    cudaFuncSetAttribute(mega_kernel, cudaFuncAttributePreferredSharedMemoryCarveout, 100);

    mega_kernel<<<GRID, NTHR, mega_sm>>>(x, enc_w1, enc_b1, enc_w2, enc_b2,
                                         gc1_w, gc1_b, gc2_w, gc2_b, gc3_w, gc3_b,
                                         cls_w1, cls_b1, cls_w2, cls_b2, out);
}

// round 17
// speedup vs baseline: 1.8463x; 1.0620x over previous
#include <cuda_runtime.h>
#include <cuda_fp16.h>
#include <cstdint>

#define SEQ 2048
#define NB  32
#define DIM 128
#define NTOK (NB*SEQ)
#define TOK 128
#define NTILES (NTOK/TOK)      // 512
#define GRID 296               // 2 CTAs/SM, all co-resident
#define NTHR 256
#define MROWS 144              // 128 tokens + 8-row halo each side
#define OFF 8                  // buffer row i <-> seq s0-8+i

// ---------------- scratch (no allocations allowed) ----------------
__device__ float g_part[NB*DIM];
__device__ __align__(16) __half g_Whi[4][DIM*DIM];
__device__ unsigned g_ctr;     // monotonic grid-barrier counter (replay-safe)

// ---------------- helpers ----------------
__device__ __forceinline__ uint32_t smem_u32(const void* p) {
    uint32_t a;
    asm("{ .reg .u64 t; cvta.to.shared.u64 t, %1; cvt.u32.u64 %0, t; }" : "=r"(a) : "l"(p));
    return a;
}
__device__ __forceinline__ void sts128(uint32_t addr, uint4 v) {
    asm volatile("st.shared.v4.b32 [%0], {%1,%2,%3,%4};" :: "r"(addr), "r"(v.x), "r"(v.y), "r"(v.z), "r"(v.w) : "memory");
}
__device__ __forceinline__ void sts32(uint32_t addr, uint32_t v) {
    asm volatile("st.shared.b32 [%0], %1;" :: "r"(addr), "r"(v) : "memory");
}
__device__ __forceinline__ uint4 lds128(uint32_t addr) {
    uint4 v;
    asm volatile("ld.shared.v4.b32 {%0,%1,%2,%3}, [%4];"
        : "=r"(v.x), "=r"(v.y), "=r"(v.z), "=r"(v.w) : "r"(addr));
    return v;
}
__device__ __forceinline__ void cpasync16(uint32_t dst, const void* src) {
    asm volatile("cp.async.cg.shared.global [%0], [%1], 16;" :: "r"(dst), "l"(src) : "memory");
}
#define CP_COMMIT() asm volatile("cp.async.commit_group;" ::: "memory")
#define CP_WAIT0()  asm volatile("cp.async.wait_group 0;" ::: "memory")
#define LDMX4(r, addr) \
    asm volatile("ldmatrix.sync.aligned.m8n8.x4.shared.b16 {%0,%1,%2,%3}, [%4];" \
        : "=r"((r)[0]), "=r"((r)[1]), "=r"((r)[2]), "=r"((r)[3]) : "r"(addr))
__device__ __forceinline__ void mma16816(float* d, const uint32_t* a, const uint32_t* b) {
    asm volatile(
        "mma.sync.aligned.m16n8k16.row.col.f32.f16.f16.f32 "
        "{%0,%1,%2,%3}, {%4,%5,%6,%7}, {%8,%9}, {%0,%1,%2,%3};"
        : "+f"(d[0]), "+f"(d[1]), "+f"(d[2]), "+f"(d[3])
        : "r"(a[0]), "r"(a[1]), "r"(a[2]), "r"(a[3]), "r"(b[0]), "r"(b[1]));
}
__device__ __forceinline__ uint32_t tswz(int row, int kchunk) {
    return (uint32_t)(row * 256 + ((kchunk ^ (row & 7)) << 4));
}
__device__ __forceinline__ uint32_t packh(float a, float b) {
    __half2 t = __floats2half2_rn(a, b);
    return *reinterpret_cast<uint32_t*>(&t);
}

// replay-safe grid barrier
__device__ __forceinline__ void grid_barrier() {
    __syncthreads();
    if (threadIdx.x == 0) {
        __threadfence();
        const unsigned t = atomicAdd(&g_ctr, 1u) + 1u;
        const unsigned target = ((t + GRID - 1u) / GRID) * GRID;
        while (atomicAdd(&g_ctr, 0u) < target) { __nanosleep(64); }
        __threadfence();
    }
    __syncthreads();
}

// ---------------------------------------------------------------------------
// ONE persistent kernel: all 4 layers fused per tile in smem, then classifier.
// 256 threads, 2 CTAs/SM. Warp grid 2m x 4n; wm=0 owns m-frags 0..4, wm=1 5..8.
// Rolling-window aggregation: each thread owns 1 chunk-col, walks 9 rows.
// ---------------------------------------------------------------------------
__global__ __launch_bounds__(NTHR, 2)
void mega_kernel(const float* __restrict__ x,
                 const float* __restrict__ enc_w1, const float* __restrict__ enc_b1,
                 const float* __restrict__ enc_w2, const float* __restrict__ enc_b2,
                 const float* __restrict__ gc1_w,  const float* __restrict__ gc1_b,
                 const float* __restrict__ gc2_w,  const float* __restrict__ gc2_b,
                 const float* __restrict__ gc3_w,  const float* __restrict__ gc3_b,
                 const float* __restrict__ cls_w1, const float* __restrict__ cls_b1,
                 const float* __restrict__ cls_w2, const float* __restrict__ cls_b2,
                 float* __restrict__ out)
{
    extern __shared__ float sm[];
    const int tid = threadIdx.x;
    const int wid = tid >> 5, lid = tid & 31;
    const uint32_t smb = smem_u32(sm);
    const uint32_t A0S = smb + 6144;        // 36KB (144 x 256B): h buffer
    const uint32_t A1S = A0S + 36864;       // 36KB: MMA-input buffer
    const uint32_t BS  = A1S + 36864;       // 32KB: weight image

    // ================= phase 0: weight prep + zero pool + headers =================
    {
        const int gid = blockIdx.x * NTHR + tid;
        if (gid < 4 * 2048) {
            const float* ws[4] = {enc_w2, gc1_w, gc2_w, gc3_w};
            const int layer = gid >> 11, c = gid & 2047;
            const float* w = ws[layer];
            __half* bh = g_Whi[layer];
            const int n = c >> 4, kc = c & 15, k0 = kc * 8;
            const int base = n * 128 + ((kc ^ (n & 7)) << 3);
            #pragma unroll
            for (int j = 0; j < 8; j++)
                bh[base + j] = __float2half_rn(w[(k0 + j) * DIM + n]);
        }
        if (gid < NB * DIM) g_part[gid] = 0.f;
    }
    // smem header: bias[4][128] @0, w1 @512, b1 @1280
    if (tid < 128) {
        sm[tid]       = enc_b2[tid];
        sm[128 + tid] = gc1_b[tid];
        sm[256 + tid] = gc2_b[tid];
        sm[384 + tid] = gc3_b[tid];
        sm[1280 + tid] = enc_b1[tid];
    }
    for (int i = tid; i < 768; i += NTHR) sm[512 + i] = enc_w1[i];
    grid_barrier();

    // lane constants
    const int wm = wid & 1, wn = wid >> 1;
    const int g = lid >> 2, t4 = lid & 3;
    const int arowl = ((lid >> 3) & 1) * 8 + (lid & 7);
    const int akcl  = lid >> 4;
    const int browl = (lid >> 4) * 8 + (lid & 7);
    const int bkcl  = (lid >> 3) & 1;
    const int mf0 = wm ? 5 : 0;
    const int NM  = wm ? 4 : 5;
    const int r2 = tid >> 1, q = tid & 1;     // enc build: 2 threads/row
    // rolling agg mapping: chunk col + 9-row strip
    const int ac = tid & 15;                  // chunk col 0..15
    const int ar0 = (tid >> 4) * 9;           // first row of strip

    // ================= tile loop: all 4 layers fused =================
    for (int tile = blockIdx.x; tile < NTILES; tile += GRID) {
        const int token0 = tile * TOK;
        const int s0 = token0 & (SEQ - 1);
        const int bb = token0 - s0;

        // ---- issue B0 (enc_w2 image) ----
        {
            const char* sh = (const char*)g_Whi[0];
            #pragma unroll
            for (int it = 0; it < 8; it++) {
                const int i = tid + it * NTHR;
                cpasync16(BS + i * 16, sh + i * 16);
            }
            CP_COMMIT();
        }

        // ---- enc layer-1 build into A1: h1 = relu(x@w1+b1), 144 rows ----
        for (int rr = r2; rr < MROWS; rr += 128) {
            const int s = s0 - OFF + rr;
            if (s >= 0 && s < SEQ) {
                float xv[6];
                const float* xr = x + (size_t)(bb + s) * 6;
                #pragma unroll
                for (int k = 0; k < 6; k++) xv[k] = xr[k];
                #pragma unroll
                for (int ch = 0; ch < 8; ch++) {
                    const int c = q * 8 + ch;
                    const int k0 = c * 8;
                    uint4 o;
                    uint32_t* po = &o.x;
                    #pragma unroll
                    for (int wd = 0; wd < 4; wd++) {
                        float v0, v1;
                        {
                            const int cc = k0 + wd * 2;
                            float a = sm[1280 + cc];
                            #pragma unroll
                            for (int k = 0; k < 6; k++) a += xv[k] * sm[512 + k * 128 + cc];
                            v0 = fmaxf(a, 0.f);
                        }
                        {
                            const int cc = k0 + wd * 2 + 1;
                            float a = sm[1280 + cc];
                            #pragma unroll
                            for (int k = 0; k < 6; k++) a += xv[k] * sm[512 + k * 128 + cc];
                            v1 = fmaxf(a, 0.f);
                        }
                        po[wd] = packh(v0, v1);
                    }
                    sts128(A1S + tswz(rr, c), o);
                }
            } else {
                #pragma unroll
                for (int ch = 0; ch < 8; ch++)
                    sts128(A1S + tswz(rr, q * 8 + ch), make_uint4(0, 0, 0, 0));
            }
        }
        CP_WAIT0();
        __syncthreads();

        // ---- 4 layers ----
        #pragma unroll 1
        for (int k = 0; k < 4; k++) {
            // rolling agg for gc layers: A0 (h) -> A1 (agg'd, scaled, OOB-zeroed)
            if (k > 0) {
                // window: prev, cur, next (clamped at buffer edges; fringe-tolerant)
                uint4 up = lds128(A0S + tswz((ar0 > 0) ? ar0 - 1 : 0, ac));
                uint4 uc = lds128(A0S + tswz(ar0, ac));
                #pragma unroll
                for (int j = 0; j < 9; j++) {
                    const int rr = ar0 + j;
                    const uint4 un = lds128(A0S + tswz((rr < MROWS - 1) ? rr + 1 : MROWS - 1, ac));
                    const int s = s0 - OFF + rr;
                    if (s >= 0 && s < SEQ) {
                        const float scf = (s == 0 || s == SEQ - 1) ? 0.5f : (1.0f / 3.0f);
                        const __half2 sc = __float2half2_rn(scf);
                        uint4 ov;
                        const uint32_t* p0 = &up.x;
                        const uint32_t* p1 = &uc.x;
                        const uint32_t* p2 = &un.x;
                        uint32_t* po = &ov.x;
                        #pragma unroll
                        for (int wd = 0; wd < 4; wd++) {
                            __half2 a = *(const __half2*)&p0[wd];
                            __half2 b = *(const __half2*)&p1[wd];
                            __half2 cc = *(const __half2*)&p2[wd];
                            __half2 sv = __hmul2(__hadd2(__hadd2(a, b), cc), sc);
                            po[wd] = *reinterpret_cast<uint32_t*>(&sv);
                        }
                        sts128(A1S + tswz(rr, ac), ov);
                    } else {
                        sts128(A1S + tswz(rr, ac), make_uint4(0, 0, 0, 0));
                    }
                    up = uc; uc = un;
                }
                __syncthreads();
            }

            // ---- GEMM: A1[144x128] x B -> acc ----
            float acc[5][4][4];
            #pragma unroll
            for (int mi = 0; mi < 5; mi++)
                #pragma unroll
                for (int ni = 0; ni < 4; ni++)
                    #pragma unroll
                    for (int j = 0; j < 4; j++) acc[mi][ni][j] = 0.f;

            #pragma unroll
            for (int ks = 0; ks < 8; ks++) {
                uint32_t ah[5][4];
                #pragma unroll
                for (int mi = 0; mi < 5; mi++)
                    if (mi < NM)
                        LDMX4(ah[mi], A1S + tswz((mf0 + mi) * 16 + arowl, ks * 2 + akcl));
                #pragma unroll
                for (int p = 0; p < 2; p++) {
                    uint32_t bf[4];
                    LDMX4(bf, BS + tswz(wn * 32 + p * 16 + browl, ks * 2 + bkcl));
                    #pragma unroll
                    for (int hn = 0; hn < 2; hn++)
                        #pragma unroll
                        for (int mi = 0; mi < 5; mi++)
                            if (mi < NM)
                                mma16816(acc[mi][p * 2 + hn], ah[mi], &bf[hn * 2]);
                }
            }
            __syncthreads();   // B consumed by all warps

            // ---- prefetch next layer's B during epilogue ----
            if (k < 3) {
                const char* sh = (const char*)g_Whi[k + 1];
                #pragma unroll
                for (int it = 0; it < 8; it++) {
                    const int i = tid + it * NTHR;
                    cpasync16(BS + i * 16, sh + i * 16);
                }
            }
            CP_COMMIT();

            // ---- epilogue ----
            if (k == 3) {
                // fused mean-pool: rows 8..135 only
                const int b = token0 >> 11;
                #pragma unroll
                for (int ni = 0; ni < 4; ni++) {
                    const int col = wn * 32 + ni * 8 + 2 * t4;
                    const float bx = sm[384 + col], by = sm[384 + col + 1];
                    float sx = 0.f, sy = 0.f;
                    #pragma unroll
                    for (int mi = 0; mi < 5; mi++) {
                        if (mi < NM) {
                            const int r0 = (mf0 + mi) * 16 + g;
                            if (r0 >= OFF && r0 < OFF + TOK) {
                                sx += fmaxf(acc[mi][ni][0] + bx, 0.f);
                                sy += fmaxf(acc[mi][ni][1] + by, 0.f);
                            }
                            if (r0 + 8 >= OFF && r0 + 8 < OFF + TOK) {
                                sx += fmaxf(acc[mi][ni][2] + bx, 0.f);
                                sy += fmaxf(acc[mi][ni][3] + by, 0.f);
                            }
                        }
                    }
                    sx += __shfl_xor_sync(0xFFFFFFFFu, sx, 16);
                    sy += __shfl_xor_sync(0xFFFFFFFFu, sy, 16);
                    sx += __shfl_xor_sync(0xFFFFFFFFu, sx, 8);
                    sy += __shfl_xor_sync(0xFFFFFFFFu, sy, 8);
                    sx += __shfl_xor_sync(0xFFFFFFFFu, sx, 4);
                    sy += __shfl_xor_sync(0xFFFFFFFFu, sy, 4);
                    if (g == 0) {
                        atomicAdd(&g_part[b * DIM + col], sx);
                        atomicAdd(&g_part[b * DIM + col + 1], sy);
                    }
                }
            } else {
                // write h = relu(acc + bias) into A0 (OOB rows -> 0)
                #pragma unroll
                for (int mi = 0; mi < 5; mi++) {
                    if (mi < NM) {
                        const int r0 = (mf0 + mi) * 16 + g;
                        const int sA = s0 - OFF + r0;
                        const int sB = sA + 8;
                        const bool vA = ((unsigned)sA < SEQ);
                        const bool vB = ((unsigned)sB < SEQ);
                        #pragma unroll
                        for (int ni = 0; ni < 4; ni++) {
                            const int col = wn * 32 + ni * 8 + 2 * t4;
                            const float bx = sm[k * 128 + col], by = sm[k * 128 + col + 1];
                            uint32_t w0 = 0, w1 = 0;
                            if (vA) {
                                float c0 = acc[mi][ni][0] + bx, c1 = acc[mi][ni][1] + by;
                                if (k > 0) { c0 = fmaxf(c0, 0.f); c1 = fmaxf(c1, 0.f); }
                                w0 = packh(c0, c1);
                            }
                            if (vB) {
                                float c2 = acc[mi][ni][2] + bx, c3 = acc[mi][ni][3] + by;
                                if (k > 0) { c2 = fmaxf(c2, 0.f); c3 = fmaxf(c3, 0.f); }
                                w1 = packh(c2, c3);
                            }
                            const uint32_t chunk = (uint32_t)(wn * 4 + ni);
                            sts32(A0S + tswz(r0, chunk) + t4 * 4, w0);
                            sts32(A0S + tswz(r0 + 8, chunk) + t4 * 4, w1);
                        }
                    }
                }
            }
            CP_WAIT0();
            __syncthreads();
        }
    }

    grid_barrier();

    // ================= classifier (CTAs 0..31) =================
    if (blockIdx.x < NB) {
        const int b = blockIdx.x;
        float* P  = sm + 1536;
        float* C1 = sm + 1664;
        if (tid < 128) P[tid] = __ldcg(&g_part[b * DIM + tid]) * (1.0f / (float)SEQ);
        __syncthreads();
        if (tid < 64) {
            float a = cls_b1[tid];
            #pragma unroll 8
            for (int k = 0; k < 128; k++) a += P[k] * cls_w1[k * 64 + tid];
            C1[tid] = fmaxf(a, 0.f);
        }
        __syncthreads();
        if (tid < 3) {
            float a = cls_b2[tid];
            #pragma unroll
            for (int k = 0; k < 64; k++) a += C1[k] * cls_w2[k * 3 + tid];
            out[b * 3 + tid] = a;
        }
    }
}

extern "C" void kernel_launch(void* const* d_in, const int* in_sizes, int n_in,
                              void* d_out, int out_size)
{
    const float* x      = (const float*)d_in[0];
    const float* enc_w1 = (const float*)d_in[1];
    const float* enc_b1 = (const float*)d_in[2];
    const float* enc_w2 = (const float*)d_in[3];
    const float* enc_b2 = (const float*)d_in[4];
    const float* gc1_w  = (const float*)d_in[5];
    const float* gc1_b  = (const float*)d_in[6];
    const float* gc2_w  = (const float*)d_in[7];
    const float* gc2_b  = (const float*)d_in[8];
    const float* gc3_w  = (const float*)d_in[9];
    const float* gc3_b  = (const float*)d_in[10];
    const float* cls_w1 = (const float*)d_in[11];
    const float* cls_b1 = (const float*)d_in[12];
    const float* cls_w2 = (const float*)d_in[13];
    const float* cls_b2 = (const float*)d_in[14];
    float* out = (float*)d_out;

    const size_t mega_sm = 6144 + 36864 * 2 + 32768;  // 112640 B -> 2 CTAs/SM
    cudaFuncSetAttribute(mega_kernel, cudaFuncAttributeMaxDynamicSharedMemorySize, (int)mega_sm);
    cudaFuncSetAttribute(mega_kernel, cudaFuncAttributePreferredSharedMemoryCarveout, 100);

    mega_kernel<<<GRID, NTHR, mega_sm>>>(x, enc_w1, enc_b1, enc_w2, enc_b2,
                                         gc1_w, gc1_b, gc2_w, gc2_b, gc3_w, gc3_b,
                                         cls_w1, cls_b1, cls_w2, cls_b2, out);
}